// round 15
// baseline (speedup 1.0000x reference)
#include <cuda_runtime.h>
#include <math.h>

#define BB 8
#define NN 4096
#define MM 1366                 // ceil(4096/3) sub-sampled centers
#define NPTS (BB*NN)            // 32768
#define NCTR (BB*MM)            // 10928
#define CPAD 2048               // centers padded to pow2 for sort

// ---- scratch (__device__ globals; no allocations allowed) ----
__device__ float4 g_pts4[NPTS];       // (x,y,z,|x|^2) orig order
__device__ float4 g_ctr4[NCTR];       // centers orig order
__device__ float4 g_spts[NPTS];       // points z-sorted per batch
__device__ int    g_sidx[NPTS];       // sorted pos -> orig point idx
__device__ float4 g_sctr[BB*CPAD];    // centers z-sorted (+sentinels w=1e38)
__device__ int    g_scidx[BB*CPAD];   // sorted pos -> orig center idx (-1 pad)
__device__ float  g_f0[NPTS*64];      // stem features
__device__ int    g_bidx[NCTR*32];    // ball-query indices (orig ids)
__device__ int    g_bcnt[NCTR];       // valid count per center
__device__ float  g_fsub[NCTR*128];   // SA max-pooled features
__device__ int    g_nn[NPTS*3];       // 3-NN center indices (orig)
__device__ float  g_wts[NPTS*3];      // interp weights
__device__ float  g_ef[NPTS*4];       // eigen features
__device__ float  g_zc[NPTS*64];      // pre-BN activations
__device__ double g_sum[64];
__device__ double g_sq[64];
__device__ float  g_mu[64];
__device__ float  g_inv[64];

// ======== stem + pts4/ctr4 build + moment zero + data copy ========
__global__ void __launch_bounds__(256) k_stem(const float* __restrict__ data,
                       const float* __restrict__ W, const float* __restrict__ bias,
                       float* __restrict__ copyOut) {
    __shared__ float Ws[192];
    __shared__ float bs[64];
    int t = threadIdx.x;
    if (t < 192) Ws[t] = W[t];
    if (t < 64)  bs[t] = bias[t];
    if (blockIdx.x == 0 && t < 128) {
        if (t < 64) g_sum[t] = 0.0; else g_sq[t-64] = 0.0;
    }
    if (copyOut && t < 12) copyOut[blockIdx.x*12 + t] = data[blockIdx.x*12 + t];
    __syncthreads();
    int r = t >> 6, c = t & 63;
    int i = blockIdx.x * 4 + r;           // global point id
    float x = data[3*i+0], y = data[3*i+1], z = data[3*i+2];
    float v = fmaf(x, Ws[c], fmaf(y, Ws[64+c], fmaf(z, Ws[128+c], bs[c])));
    g_f0[(size_t)i*64 + c] = fmaxf(v, 0.f);
    if (c == 0) {
        float n2 = (x*x + y*y) + z*z;
        float4 p = make_float4(x, y, z, n2);
        g_pts4[i] = p;
        int n = i & (NN-1), b = i >> 12;
        if (n % 3 == 0) g_ctr4[b*MM + n/3] = p;
    }
}

// ======== per-batch bitonic sort by z: points (bid<8) and centers ========
__global__ void __launch_bounds__(1024) k_sort() {
    __shared__ float kz[4096];
    __shared__ int   ki[4096];
    int t = threadIdx.x;
    int bid = blockIdx.x;
    if (bid < BB) {
        int b = bid;
        for (int e = t; e < NN; e += 1024) { kz[e] = g_pts4[(size_t)b*NN+e].z; ki[e] = e; }
        for (int k = 2; k <= NN; k <<= 1)
            for (int j = k >> 1; j > 0; j >>= 1) {
                __syncthreads();
                for (int i = t; i < NN; i += 1024) {
                    int ixj = i ^ j;
                    if (ixj > i) {
                        bool asc = ((i & k) == 0);
                        float a = kz[i], c = kz[ixj];
                        bool sw = asc ? (a > c) : (a < c);
                        if (sw) { kz[i] = c; kz[ixj] = a;
                                  int tt = ki[i]; ki[i] = ki[ixj]; ki[ixj] = tt; }
                    }
                }
            }
        __syncthreads();
        for (int e = t; e < NN; e += 1024) {
            int src = ki[e];
            g_spts[(size_t)b*NN + e] = g_pts4[(size_t)b*NN + src];
            g_sidx[(size_t)b*NN + e] = src;
        }
    } else {
        int b = bid - BB;
        for (int e = t; e < CPAD; e += 1024) {
            if (e < MM) { kz[e] = g_ctr4[b*MM + e].z; ki[e] = e; }
            else        { kz[e] = 1e19f; ki[e] = -1; }
        }
        for (int k = 2; k <= CPAD; k <<= 1)
            for (int j = k >> 1; j > 0; j >>= 1) {
                __syncthreads();
                for (int i = t; i < CPAD; i += 1024) {
                    int ixj = i ^ j;
                    if (ixj > i) {
                        bool asc = ((i & k) == 0);
                        float a = kz[i], c = kz[ixj];
                        bool sw = asc ? (a > c) : (a < c);
                        if (sw) { kz[i] = c; kz[ixj] = a;
                                  int tt = ki[i]; ki[i] = ki[ixj]; ki[ixj] = tt; }
                    }
                }
            }
        __syncthreads();
        for (int e = t; e < CPAD; e += 1024) {
            int src = ki[e];
            g_sctr[b*CPAD + e] = (src >= 0) ? g_ctr4[b*MM + src]
                                            : make_float4(0.f, 0.f, 1e19f, 1e38f);
            g_scidx[b*CPAD + e] = src;
        }
    }
}

// ======== ball query: warp-per-center over z-window of sorted points ========
__global__ void __launch_bounds__(512) k_ball() {
    const int CPB = 86;                   // ceil(MM/16) blocks per batch
    int b  = blockIdx.x / CPB;
    int m  = (blockIdx.x % CPB) * 16 + (threadIdx.x >> 5);   // sorted center pos
    int lane = threadIdx.x & 31;
    if (m >= MM) return;
    float4 cc = g_sctr[b*CPAD + m];
    int cid = g_scidx[b*CPAD + m];        // orig center index
    int gw = b*MM + cid;
    float cx = cc.x, cy = cc.y, cz = cc.z, cn2 = cc.w;
    const float R2 = 0.01f;
    const float4* pb = g_spts + (size_t)b*NN;
    const int* si = g_sidx + (size_t)b*NN;
    float tgt = cz - 0.101f;
    int lo = 0, hi = NN;
    while (lo < hi) { int mid = (lo + hi) >> 1; if (pb[mid].z < tgt) lo = mid + 1; else hi = mid; }
    float zhi = cz + 0.101f;
    int cnt = 0, first = 0x7fffffff;
    for (int j0 = lo; ; j0 += 32) {
        int j = j0 + lane;
        bool inw = false, valid = false; int oi = 0x7fffffff;
        if (j < NN) {
            float4 p = pb[j];
            if (p.z <= zhi) {
                inw = true;
                float dt = (cx*p.x + cy*p.y) + cz*p.z;
                float d2 = cn2 + p.w - 2.f*dt;
                if (d2 < R2) { valid = true; oi = si[j]; }
            }
        }
        if (__ballot_sync(0xffffffffu, inw) == 0u) break;
        unsigned vm = __ballot_sync(0xffffffffu, valid);
        if (vm) {
            int mn = __reduce_min_sync(0xffffffffu, oi);
            first = min(first, mn);
            int pos = cnt + __popc(vm & ((1u << lane) - 1u));
            if (valid && pos < 32) g_bidx[gw*32 + pos] = oi;
            cnt += __popc(vm);
        }
    }
    if (cnt > 32) cnt = 32;
    for (int s = cnt + lane; s < 32; s += 32) g_bidx[gw*32 + s] = first;
    if (lane == 0) g_bcnt[gw] = cnt;
}

// ====== SA conv + max: 8 centers/block, 2-way ILP over samples ======
__global__ void __launch_bounds__(128) k_sa(const float* __restrict__ W,
                                            const float* __restrict__ bias) {
    __shared__ float feat[32][68];
    int t = threadIdx.x;
    float w[67];
#pragma unroll
    for (int j = 0; j < 67; ++j) w[j] = W[j*128 + t];
    float bb = bias[t];
    const float* p4 = (const float*)g_pts4;
#pragma unroll 1
    for (int s = 0; s < 8; ++s) {
        int cid = blockIdx.x*8 + s;
        int b = cid / MM;
        int cnt = g_bcnt[cid];
        float4 cc = g_ctr4[cid];
        __syncthreads();
        for (int i = t; i < cnt*64; i += 128) {
            int k = i >> 6, c = i & 63;
            int idx = g_bidx[cid*32 + k];
            feat[k][3+c] = g_f0[((size_t)b*NN + idx)*64 + c];
        }
        for (int i = t; i < cnt*3; i += 128) {
            int k = i/3, c = i - k*3;
            int idx = g_bidx[cid*32 + k];
            float pv = p4[((size_t)b*NN + idx)*4 + c];
            float cv = (c == 0) ? cc.x : ((c == 1) ? cc.y : cc.z);
            feat[k][c] = (pv - cv) / 0.1f;
        }
        __syncthreads();
        float mx = 0.f;                   // relu >= 0 so max-with-0 exact
        int k = 0;
        for (; k + 2 <= cnt; k += 2) {    // two independent chains (ILP)
            float a0 = bb, a1 = bb;
#pragma unroll
            for (int j = 0; j < 67; ++j) {
                a0 = fmaf(feat[k][j],   w[j], a0);
                a1 = fmaf(feat[k+1][j], w[j], a1);
            }
            mx = fmaxf(mx, fmaxf(a0, a1));
        }
        if (k < cnt) {
            float a0 = bb;
#pragma unroll
            for (int j = 0; j < 67; ++j) a0 = fmaf(feat[k][j], w[j], a0);
            mx = fmaxf(mx, a0);
        }
        g_fsub[(size_t)cid*128 + t] = mx;
    }
}

// ---- insert / score macros ----
#define SC(q) fmaf(px2, (q).x, fmaf(py2, (q).y, fmaf(pz2, (q).z, (q).w)))

#define INS3(s, jj) \
    if ((s) < d2v) { \
        if ((s) < d1) { d2v = d1; i2 = i1; \
            if ((s) < d0) { d1 = d0; i1 = i0; d0 = (s); i0 = (jj); } \
            else          { d1 = (s); i1 = (jj); } } \
        else { d2v = (s); i2 = (jj); } }

#define MAX10 dmax = fmaxf(fmaxf(fmaxf(fmaxf(d[0],d[1]),fmaxf(d[2],d[3])), \
                     fmaxf(fmaxf(d[4],d[5]),fmaxf(d[6],d[7]))),fmaxf(d[8],d[9]));

#define REP10(s, jj) { \
    float _m = dmax; \
    _Pragma("unroll") \
    for (int k = 0; k < 10; ++k) { if (d[k] == _m) { d[k] = (s); id[k] = (jj); } } \
    MAX10 \
}

#define EGRP8(jj, off) { \
    float4 q0 = sj[jj],   q1 = sj[(jj)+1], q2 = sj[(jj)+2], q3 = sj[(jj)+3]; \
    float4 q4 = sj[(jj)+4], q5 = sj[(jj)+5], q6 = sj[(jj)+6], q7 = sj[(jj)+7]; \
    float s0 = SC(q0), s1 = SC(q1), s2 = SC(q2), s3 = SC(q3); \
    float s4 = SC(q4), s5 = SC(q5), s6 = SC(q6), s7 = SC(q7); \
    float m8 = fminf(fminf(fminf(s0,s1), fminf(s2,s3)), \
                     fminf(fminf(s4,s5), fminf(s6,s7))); \
    if (m8 < dmax) { \
        if (s0 < dmax) REP10(s0, (off)+(jj)) \
        if (s1 < dmax) REP10(s1, (off)+(jj)+1) \
        if (s2 < dmax) REP10(s2, (off)+(jj)+2) \
        if (s3 < dmax) REP10(s3, (off)+(jj)+3) \
        if (s4 < dmax) REP10(s4, (off)+(jj)+4) \
        if (s5 < dmax) REP10(s5, (off)+(jj)+5) \
        if (s6 < dmax) REP10(s6, (off)+(jj)+6) \
        if (s7 < dmax) REP10(s7, (off)+(jj)+7) \
    } \
}

#define KSCAN128(base) { \
    for (int j = 0; j < 128; j += 8) { \
        float4 q0 = scc[j],   q1 = scc[j+1], q2 = scc[j+2], q3 = scc[j+3]; \
        float4 q4 = scc[j+4], q5 = scc[j+5], q6 = scc[j+6], q7 = scc[j+7]; \
        float s0 = SC(q0), s1 = SC(q1), s2 = SC(q2), s3 = SC(q3); \
        float s4 = SC(q4), s5 = SC(q5), s6 = SC(q6), s7 = SC(q7); \
        float m8 = fminf(fminf(fminf(s0,s1), fminf(s2,s3)), \
                         fminf(fminf(s4,s5), fminf(s6,s7))); \
        if (m8 < d2v) { \
            INS3(s0, (base)+j)   INS3(s1, (base)+j+1) INS3(s2, (base)+j+2) INS3(s3, (base)+j+3) \
            INS3(s4, (base)+j+4) INS3(s5, (base)+j+5) INS3(s6, (base)+j+6) INS3(s7, (base)+j+7) \
        } \
    } }

// ======== 3-NN: 128-center chunks over sorted centers, ring order ========
__global__ void __launch_bounds__(256) k_knn3() {
    __shared__ float4 scc[128];
    int blk = blockIdx.x;
    int b = blk >> 4, l = blk & 15;
    int q = (l << 8) + threadIdx.x;
    const float4* pb = g_spts + (size_t)b*NN;
    const float4* cb = g_sctr + b*CPAD;
    float4 pp = pb[q];
    int pid = (b << 12) + g_sidx[(size_t)b*NN + q];
    float zi = pp.z, pn2 = pp.w;
    float px2 = -2.f*pp.x, py2 = -2.f*pp.y, pz2 = -2.f*pp.z;
    float d0 = 1e37f, d1 = 1e37f, d2v = 1e37f;
    int i0 = 0, i1 = 0, i2 = 0;
    int qm = (l << 8) + 128;
    int c0 = (qm * MM / NN) >> 7; if (c0 > 10) c0 = 10;   // block-uniform, 0..10
    // own chunk
    {
        int base = c0 << 7;
        if (threadIdx.x < 128) scc[threadIdx.x] = cb[base + threadIdx.x];
        __syncthreads();
        KSCAN128(base)
    }
    bool needL = true, needR = true;
#pragma unroll 1
    for (int step = 1; step <= 15; ++step) {
        int cl = c0 - step, cr = c0 + step;
        {   // left
            bool far = true;
            if (needL && cl >= 0) {
                float ze = cb[(cl << 7) + 127].z;
                float dz = zi - ze;
                far = (dz > 0.f) && (dz*dz > fmaf(d2v + pn2, 1.0001f, 1e-9f));
            }
            if (__syncthreads_and(far)) needL = false;
            if (needL && cl >= 0) {
                int base = cl << 7;
                __syncthreads();
                if (threadIdx.x < 128) scc[threadIdx.x] = cb[base + threadIdx.x];
                __syncthreads();
                KSCAN128(base)
            }
        }
        {   // right
            bool far = true;
            if (needR && cr < 16) {
                float ze = cb[cr << 7].z;
                float dz = ze - zi;
                far = (dz > 0.f) && (dz*dz > fmaf(d2v + pn2, 1.0001f, 1e-9f));
            }
            if (__syncthreads_and(far)) needR = false;
            if (needR && cr < 16) {
                int base = cr << 7;
                __syncthreads();
                if (threadIdx.x < 128) scc[threadIdx.x] = cb[base + threadIdx.x];
                __syncthreads();
                KSCAN128(base)
            }
        }
        if (!needL && !needR) break;
    }
    i0 = g_scidx[b*CPAD + i0];
    i1 = g_scidx[b*CPAD + i1];
    i2 = g_scidx[b*CPAD + i2];
    float D0 = d0 + pn2, D1 = d1 + pn2, D2 = d2v + pn2;
    float w0 = 1.f/(D0 + 1e-8f), w1 = 1.f/(D1 + 1e-8f), w2 = 1.f/(D2 + 1e-8f);
    float ws = (w0 + w1) + w2;
    w0 /= ws; w1 /= ws; w2 /= ws;
    g_nn[pid*3+0] = i0; g_nn[pid*3+1] = i1; g_nn[pid*3+2] = i2;
    g_wts[pid*3+0] = w0; g_wts[pid*3+1] = w1; g_wts[pid*3+2] = w2;
}

// ===== 10-NN: 128-point chunks (dual own-chunk), ring + cov/eig/MLP =====
__global__ void __launch_bounds__(256) k_eig(
        const float* __restrict__ We1, const float* __restrict__ be1,
        const float* __restrict__ We2, const float* __restrict__ be2) {
    __shared__ float4 sj[128];            // 2KB
    int blk = blockIdx.x;
    int b = blk >> 4, l = blk & 15;
    int q = (l << 8) + threadIdx.x;
    const float4* pb = g_spts + (size_t)b*NN;
    float4 pp = pb[q];
    int pid = (b << 12) + g_sidx[(size_t)b*NN + q];
    float zi = pp.z, pn2 = pp.w;
    float px2 = -2.f*pp.x, py2 = -2.f*pp.y, pz2 = -2.f*pp.z;
    float d[10]; int id[10];
#pragma unroll
    for (int k = 0; k < 10; ++k) { d[k] = 1e37f + (float)k*1e33f; id[k] = q; }
    float dmax = d[9];
    int c0 = l << 1;                      // block's queries span chunks 2l, 2l+1
#pragma unroll 1
    for (int o = 0; o < 2; ++o) {
        int base = (c0 + o) << 7;
        __syncthreads();
        if (threadIdx.x < 128) sj[threadIdx.x] = pb[base + threadIdx.x];
        __syncthreads();
        for (int j = 0; j < 128; j += 8) { EGRP8(j, base) }
    }
    bool needL = true, needR = true;
#pragma unroll 1
    for (int step = 1; step <= 31; ++step) {
        int cl = c0 - step, cr = c0 + 1 + step;
        {   // left
            bool far = true;
            if (needL && cl >= 0) {
                float ze = pb[(cl << 7) + 127].z;
                float dz = zi - ze;
                far = (dz > 0.f) && (dz*dz > fmaf(dmax + pn2, 1.0001f, 1e-9f));
            }
            if (__syncthreads_and(far)) needL = false;
            if (needL && cl >= 0) {
                int base = cl << 7;
                __syncthreads();
                if (threadIdx.x < 128) sj[threadIdx.x] = pb[base + threadIdx.x];
                __syncthreads();
                for (int j = 0; j < 128; j += 8) { EGRP8(j, base) }
            }
        }
        {   // right
            bool far = true;
            if (needR && cr < 32) {
                float ze = pb[cr << 7].z;
                float dz = ze - zi;
                far = (dz > 0.f) && (dz*dz > fmaf(dmax + pn2, 1.0001f, 1e-9f));
            }
            if (__syncthreads_and(far)) needR = false;
            if (needR && cr < 32) {
                int base = cr << 7;
                __syncthreads();
                if (threadIdx.x < 128) sj[threadIdx.x] = pb[base + threadIdx.x];
                __syncthreads();
                for (int j = 0; j < 128; j += 8) { EGRP8(j, base) }
            }
        }
        if (!(needL | needR)) break;
    }
    // gather + mean + covariance (order-invariant)
    float nx[10], ny[10], nz[10];
    float mx = 0.f, my = 0.f, mz = 0.f;
#pragma unroll
    for (int k = 0; k < 10; ++k) {
        float4 qq = pb[id[k]];
        nx[k] = qq.x; ny[k] = qq.y; nz[k] = qq.z;
        mx += qq.x; my += qq.y; mz += qq.z;
    }
    mx /= 10.f; my /= 10.f; mz /= 10.f;
    float cxx=0,cxy=0,cxz=0,cyy=0,cyz=0,czz=0;
#pragma unroll
    for (int k = 0; k < 10; ++k) {
        float dx = nx[k]-mx, dy = ny[k]-my, dz = nz[k]-mz;
        cxx += dx*dx; cxy += dx*dy; cxz += dx*dz;
        cyy += dy*dy; cyz += dy*dz; czz += dz*dz;
    }
    cxx /= 10.f; cxy /= 10.f; cxz /= 10.f; cyy /= 10.f; cyz /= 10.f; czz /= 10.f;
    // analytic symmetric 3x3 eigvalsh in fp64, ascending
    double a00=cxx, a01=cxy, a02=cxz, a11=cyy, a12=cyz, a22=czz;
    double qd  = (a00 + a11 + a22) / 3.0;
    double p1 = a01*a01 + a02*a02 + a12*a12;
    double b00 = a00 - qd, b11 = a11 - qd, b22 = a22 - qd;
    double p2 = b00*b00 + b11*b11 + b22*b22 + 2.0*p1;
    double e0, e1, e2;
    if (p2 < 1e-60) { e0 = e1 = e2 = qd; }
    else {
        double p  = sqrt(p2 / 6.0);
        double ip = 1.0 / p;
        double c00=b00*ip, c11=b11*ip, c22=b22*ip, c01=a01*ip, c02=a02*ip, c12=a12*ip;
        double detB = c00*(c11*c22 - c12*c12) - c01*(c01*c22 - c12*c02)
                    + c02*(c01*c12 - c11*c02);
        double r = 0.5 * detB;
        r = fmin(1.0, fmax(-1.0, r));
        double phi = acos(r) / 3.0;
        double l1 = qd + 2.0*p*cos(phi);
        double l3 = qd + 2.0*p*cos(phi + 2.0943951023931953);
        double l2 = 3.0*qd - l1 - l3;
        e0 = l3; e1 = l2; e2 = l1;        // ascending
    }
    float ev0 = (float)e0, ev1 = (float)e1, ev2 = (float)e2;
    float hh[4];
#pragma unroll
    for (int i = 0; i < 4; ++i) {
        float v = fmaf(ev0, We1[i], fmaf(ev1, We1[4+i], fmaf(ev2, We1[8+i], be1[i])));
        hh[i] = fmaxf(v, 0.f);
    }
#pragma unroll
    for (int i = 0; i < 4; ++i) {
        float v = be2[i];
#pragma unroll
        for (int j = 0; j < 4; ++j) v = fmaf(hh[j], We2[j*4+i], v);
        g_ef[(size_t)pid*4 + i] = v;
    }
}

// ==== fused interp+FP+final-linear: 64 pts/block, 4x4 register blocking ====
__global__ void __launch_bounds__(256) k_fpzc(
        const float* __restrict__ W,  const float* __restrict__ bias,
        const float* __restrict__ W2, const float* __restrict__ bias2) {
    __shared__ float fs[64][196];         // 50176 B (reused for zc input)
    __shared__ float ssum[64], ssq[64];
    int t = threadIdx.x;
    int g = t >> 4, q = t & 15;
    size_t base = (size_t)blockIdx.x * 64;
#pragma unroll
    for (int i = 0; i < 4; ++i) {
        int p = g*4 + i;
        size_t pid = base + p;
        int b = (int)(pid >> 12);
        int n0 = g_nn[pid*3+0], n1 = g_nn[pid*3+1], n2 = g_nn[pid*3+2];
        float w0 = g_wts[pid*3+0], w1 = g_wts[pid*3+1], w2 = g_wts[pid*3+2];
        size_t a0 = ((size_t)b*MM + n0)*128;
        size_t a1 = ((size_t)b*MM + n1)*128;
        size_t a2 = ((size_t)b*MM + n2)*128;
#pragma unroll
        for (int k = 0; k < 8; ++k) {
            int j = k*16 + q;
            fs[p][j] = (w0*g_fsub[a0+j] + w1*g_fsub[a1+j]) + w2*g_fsub[a2+j];
        }
#pragma unroll
        for (int k = 0; k < 4; ++k) {
            int j = k*16 + q;
            fs[p][128+j] = g_f0[pid*64 + j];
        }
    }
    if (t < 64) { ssum[t] = 0.f; ssq[t] = 0.f; }
    __syncthreads();
    int c4 = q*4;
    int p0 = g*4;
    float4 bi = *(const float4*)&bias[c4];
    float4 a0 = bi, a1 = bi, a2 = bi, a3 = bi;
#pragma unroll 4
    for (int j = 0; j < 192; ++j) {
        float4 w4 = *(const float4*)&W[j*64 + c4];
        float v0 = fs[p0+0][j], v1 = fs[p0+1][j], v2 = fs[p0+2][j], v3 = fs[p0+3][j];
        a0.x = fmaf(v0, w4.x, a0.x); a0.y = fmaf(v0, w4.y, a0.y);
        a0.z = fmaf(v0, w4.z, a0.z); a0.w = fmaf(v0, w4.w, a0.w);
        a1.x = fmaf(v1, w4.x, a1.x); a1.y = fmaf(v1, w4.y, a1.y);
        a1.z = fmaf(v1, w4.z, a1.z); a1.w = fmaf(v1, w4.w, a1.w);
        a2.x = fmaf(v2, w4.x, a2.x); a2.y = fmaf(v2, w4.y, a2.y);
        a2.z = fmaf(v2, w4.z, a2.z); a2.w = fmaf(v2, w4.w, a2.w);
        a3.x = fmaf(v3, w4.x, a3.x); a3.y = fmaf(v3, w4.y, a3.y);
        a3.z = fmaf(v3, w4.z, a3.z); a3.w = fmaf(v3, w4.w, a3.w);
    }
    __syncthreads();                      // all reads of fs done
    *(float4*)&fs[p0+0][c4] = make_float4(fmaxf(a0.x,0.f), fmaxf(a0.y,0.f), fmaxf(a0.z,0.f), fmaxf(a0.w,0.f));
    *(float4*)&fs[p0+1][c4] = make_float4(fmaxf(a1.x,0.f), fmaxf(a1.y,0.f), fmaxf(a1.z,0.f), fmaxf(a1.w,0.f));
    *(float4*)&fs[p0+2][c4] = make_float4(fmaxf(a2.x,0.f), fmaxf(a2.y,0.f), fmaxf(a2.z,0.f), fmaxf(a2.w,0.f));
    *(float4*)&fs[p0+3][c4] = make_float4(fmaxf(a3.x,0.f), fmaxf(a3.y,0.f), fmaxf(a3.z,0.f), fmaxf(a3.w,0.f));
    if (q < 4) {
#pragma unroll
        for (int i = 0; i < 4; ++i)
            fs[p0+i][64+q] = g_ef[(base+p0+i)*4 + q];
    }
    __syncthreads();
    float4 bi2 = *(const float4*)&bias2[c4];
    a0 = bi2; a1 = bi2; a2 = bi2; a3 = bi2;
#pragma unroll
    for (int j = 0; j < 68; ++j) {
        float4 w4 = *(const float4*)&W2[j*64 + c4];
        float v0 = fs[p0+0][j], v1 = fs[p0+1][j], v2 = fs[p0+2][j], v3 = fs[p0+3][j];
        a0.x = fmaf(v0, w4.x, a0.x); a0.y = fmaf(v0, w4.y, a0.y);
        a0.z = fmaf(v0, w4.z, a0.z); a0.w = fmaf(v0, w4.w, a0.w);
        a1.x = fmaf(v1, w4.x, a1.x); a1.y = fmaf(v1, w4.y, a1.y);
        a1.z = fmaf(v1, w4.z, a1.z); a1.w = fmaf(v1, w4.w, a1.w);
        a2.x = fmaf(v2, w4.x, a2.x); a2.y = fmaf(v2, w4.y, a2.y);
        a2.z = fmaf(v2, w4.z, a2.z); a2.w = fmaf(v2, w4.w, a2.w);
        a3.x = fmaf(v3, w4.x, a3.x); a3.y = fmaf(v3, w4.y, a3.y);
        a3.z = fmaf(v3, w4.z, a3.z); a3.w = fmaf(v3, w4.w, a3.w);
    }
    *(float4*)&g_zc[(base+p0+0)*64 + c4] = a0;
    *(float4*)&g_zc[(base+p0+1)*64 + c4] = a1;
    *(float4*)&g_zc[(base+p0+2)*64 + c4] = a2;
    *(float4*)&g_zc[(base+p0+3)*64 + c4] = a3;
    float sx = ((a0.x + a1.x) + (a2.x + a3.x));
    float sy = ((a0.y + a1.y) + (a2.y + a3.y));
    float sz = ((a0.z + a1.z) + (a2.z + a3.z));
    float sw = ((a0.w + a1.w) + (a2.w + a3.w));
    float qx = ((a0.x*a0.x + a1.x*a1.x) + (a2.x*a2.x + a3.x*a3.x));
    float qy = ((a0.y*a0.y + a1.y*a1.y) + (a2.y*a2.y + a3.y*a3.y));
    float qz = ((a0.z*a0.z + a1.z*a1.z) + (a2.z*a2.z + a3.z*a3.z));
    float qw = ((a0.w*a0.w + a1.w*a1.w) + (a2.w*a2.w + a3.w*a3.w));
    atomicAdd(&ssum[c4+0], sx); atomicAdd(&ssum[c4+1], sy);
    atomicAdd(&ssum[c4+2], sz); atomicAdd(&ssum[c4+3], sw);
    atomicAdd(&ssq[c4+0], qx);  atomicAdd(&ssq[c4+1], qy);
    atomicAdd(&ssq[c4+2], qz);  atomicAdd(&ssq[c4+3], qw);
    __syncthreads();
    if (t < 64) {
        atomicAdd(&g_sum[t], (double)ssum[t]);
        atomicAdd(&g_sq[t],  (double)ssq[t]);
    }
}

__global__ void k_stats() {
    int c = threadIdx.x;
    if (c < 64) {
        double mu  = g_sum[c] / (double)NPTS;
        double var = g_sq[c] / (double)NPTS - mu*mu;
        g_mu[c]  = (float)mu;
        g_inv[c] = rsqrtf((float)var + 1e-5f);
    }
}

// ======= normalize + relu + transpose via smem tiles =======
__global__ void k_norm(const float* __restrict__ gamma, const float* __restrict__ beta,
                       float* __restrict__ outz) {
    __shared__ float tile[32][33];
    int b   = blockIdx.x >> 8;            // 256 blocks per batch
    int rem = blockIdx.x & 255;
    int ct  = rem >> 7;                   // 2 channel tiles
    int nt  = rem & 127;                  // 128 point tiles
    int tx = threadIdx.x, ty = threadIdx.y;
    int c = ct*32 + tx;
    float mu = g_mu[c], inv = g_inv[c], ga = gamma[c], be = beta[c];
#pragma unroll
    for (int i = 0; i < 4; ++i) {
        int n = nt*32 + ty + i*8;
        float v = g_zc[(((size_t)(b<<12) + n) << 6) + c];
        v = (v - mu) * inv * ga + be;
        tile[ty + i*8][tx] = fmaxf(v, 0.f);
    }
    __syncthreads();
#pragma unroll
    for (int i = 0; i < 4; ++i) {
        int cc = ct*32 + ty + i*8;
        int n  = nt*32 + tx;
        outz[(((size_t)b*64 + cc) << 12) + n] = tile[tx][ty + i*8];
    }
}

// ================= launch =================
extern "C" void kernel_launch(void* const* d_in, const int* in_sizes, int n_in,
                              void* d_out, int out_size) {
    const float* data = (const float*)d_in[0];
    int o = 1;
    if (n_in >= 16 && in_sizes[1] == 1) o = 2;   // skip scalar 'numpoints'
    const float* W_stem = (const float*)d_in[o+0];
    const float* b_stem = (const float*)d_in[o+1];
    const float* W_sa   = (const float*)d_in[o+2];
    const float* b_sa   = (const float*)d_in[o+3];
    const float* W_fp   = (const float*)d_in[o+4];
    const float* b_fp   = (const float*)d_in[o+5];
    const float* W_e1   = (const float*)d_in[o+6];
    const float* b_e1   = (const float*)d_in[o+7];
    const float* W_e2   = (const float*)d_in[o+8];
    const float* b_e2   = (const float*)d_in[o+9];
    const float* W_fin  = (const float*)d_in[o+10];
    const float* b_fin  = (const float*)d_in[o+11];
    const float* gamma  = (const float*)d_in[o+12];
    const float* beta   = (const float*)d_in[o+13];
    float* out = (float*)d_out;
    size_t zoff = ((size_t)out_size == (size_t)BB*64*NN) ? 0 : (size_t)NPTS*3;

    k_stem<<<NPTS/4, 256>>>(data, W_stem, b_stem, zoff ? out : (float*)0);
    k_sort<<<2*BB, 1024>>>();
    k_ball<<<BB*86, 512>>>();
    k_sa<<<NCTR/8, 128>>>(W_sa, b_sa);
    k_knn3<<<NPTS/256, 256>>>();
    k_eig<<<NPTS/256, 256>>>(W_e1, b_e1, W_e2, b_e2);
    k_fpzc<<<NPTS/64, 256>>>(W_fp, b_fp, W_fin, b_fin);
    k_stats<<<1, 64>>>();
    dim3 nb(32, 8);
    k_norm<<<BB*256, nb>>>(gamma, beta, out + zoff);
}

// round 16
// speedup vs baseline: 1.0480x; 1.0480x over previous
#include <cuda_runtime.h>
#include <math.h>

#define BB 8
#define NN 4096
#define MM 1366                 // ceil(4096/3) sub-sampled centers
#define NPTS (BB*NN)            // 32768
#define NCTR (BB*MM)            // 10928
#define CPAD 2048               // centers padded to pow2 for sort

// ---- scratch (__device__ globals; no allocations allowed) ----
__device__ float4 g_pts4[NPTS];       // (x,y,z,|x|^2) orig order
__device__ float4 g_ctr4[NCTR];       // centers orig order
__device__ float4 g_spts[NPTS];       // points z-sorted per batch
__device__ int    g_sidx[NPTS];       // sorted pos -> orig point idx
__device__ float4 g_sctr[BB*CPAD];    // centers z-sorted (+sentinels w=1e38)
__device__ int    g_scidx[BB*CPAD];   // sorted pos -> orig center idx (-1 pad)
__device__ float  g_f0[NPTS*64];      // stem features
__device__ int    g_bidx[NCTR*32];    // ball-query indices (orig ids)
__device__ int    g_bcnt[NCTR];       // valid count per center
__device__ float  g_fsub[NCTR*128];   // SA max-pooled features
__device__ int    g_nn[NPTS*3];       // 3-NN center indices (orig)
__device__ float  g_wts[NPTS*3];      // interp weights
__device__ float  g_ef[NPTS*4];       // eigen features
__device__ float  g_zc[NPTS*64];      // pre-BN activations
__device__ double g_sum[64];
__device__ double g_sq[64];
__device__ float  g_mu[64];
__device__ float  g_inv[64];

// ======== stem + pts4/ctr4 build + moment zero + data copy ========
__global__ void __launch_bounds__(256) k_stem(const float* __restrict__ data,
                       const float* __restrict__ W, const float* __restrict__ bias,
                       float* __restrict__ copyOut) {
    __shared__ float Ws[192];
    __shared__ float bs[64];
    int t = threadIdx.x;
    if (t < 192) Ws[t] = W[t];
    if (t < 64)  bs[t] = bias[t];
    if (blockIdx.x == 0 && t < 128) {
        if (t < 64) g_sum[t] = 0.0; else g_sq[t-64] = 0.0;
    }
    if (copyOut && t < 12) copyOut[blockIdx.x*12 + t] = data[blockIdx.x*12 + t];
    __syncthreads();
    int r = t >> 6, c = t & 63;
    int i = blockIdx.x * 4 + r;           // global point id
    float x = data[3*i+0], y = data[3*i+1], z = data[3*i+2];
    float v = fmaf(x, Ws[c], fmaf(y, Ws[64+c], fmaf(z, Ws[128+c], bs[c])));
    g_f0[(size_t)i*64 + c] = fmaxf(v, 0.f);
    if (c == 0) {
        float n2 = (x*x + y*y) + z*z;
        float4 p = make_float4(x, y, z, n2);
        g_pts4[i] = p;
        int n = i & (NN-1), b = i >> 12;
        if (n % 3 == 0) g_ctr4[b*MM + n/3] = p;
    }
}

// ======== per-batch bitonic sort by z: points (bid<8) and centers ========
__global__ void __launch_bounds__(1024) k_sort() {
    __shared__ float kz[4096];
    __shared__ int   ki[4096];
    int t = threadIdx.x;
    int bid = blockIdx.x;
    if (bid < BB) {
        int b = bid;
        for (int e = t; e < NN; e += 1024) { kz[e] = g_pts4[(size_t)b*NN+e].z; ki[e] = e; }
        for (int k = 2; k <= NN; k <<= 1)
            for (int j = k >> 1; j > 0; j >>= 1) {
                __syncthreads();
                for (int i = t; i < NN; i += 1024) {
                    int ixj = i ^ j;
                    if (ixj > i) {
                        bool asc = ((i & k) == 0);
                        float a = kz[i], c = kz[ixj];
                        bool sw = asc ? (a > c) : (a < c);
                        if (sw) { kz[i] = c; kz[ixj] = a;
                                  int tt = ki[i]; ki[i] = ki[ixj]; ki[ixj] = tt; }
                    }
                }
            }
        __syncthreads();
        for (int e = t; e < NN; e += 1024) {
            int src = ki[e];
            g_spts[(size_t)b*NN + e] = g_pts4[(size_t)b*NN + src];
            g_sidx[(size_t)b*NN + e] = src;
        }
    } else {
        int b = bid - BB;
        for (int e = t; e < CPAD; e += 1024) {
            if (e < MM) { kz[e] = g_ctr4[b*MM + e].z; ki[e] = e; }
            else        { kz[e] = 1e19f; ki[e] = -1; }
        }
        for (int k = 2; k <= CPAD; k <<= 1)
            for (int j = k >> 1; j > 0; j >>= 1) {
                __syncthreads();
                for (int i = t; i < CPAD; i += 1024) {
                    int ixj = i ^ j;
                    if (ixj > i) {
                        bool asc = ((i & k) == 0);
                        float a = kz[i], c = kz[ixj];
                        bool sw = asc ? (a > c) : (a < c);
                        if (sw) { kz[i] = c; kz[ixj] = a;
                                  int tt = ki[i]; ki[i] = ki[ixj]; ki[ixj] = tt; }
                    }
                }
            }
        __syncthreads();
        for (int e = t; e < CPAD; e += 1024) {
            int src = ki[e];
            g_sctr[b*CPAD + e] = (src >= 0) ? g_ctr4[b*MM + src]
                                            : make_float4(0.f, 0.f, 1e19f, 1e38f);
            g_scidx[b*CPAD + e] = src;
        }
    }
}

// ======== ball query: warp-per-center over z-window of sorted points ========
__global__ void __launch_bounds__(512) k_ball() {
    const int CPB = 86;                   // ceil(MM/16) blocks per batch
    int b  = blockIdx.x / CPB;
    int m  = (blockIdx.x % CPB) * 16 + (threadIdx.x >> 5);   // sorted center pos
    int lane = threadIdx.x & 31;
    if (m >= MM) return;
    float4 cc = g_sctr[b*CPAD + m];
    int cid = g_scidx[b*CPAD + m];        // orig center index
    int gw = b*MM + cid;
    float cx = cc.x, cy = cc.y, cz = cc.z, cn2 = cc.w;
    const float R2 = 0.01f;
    const float4* pb = g_spts + (size_t)b*NN;
    const int* si = g_sidx + (size_t)b*NN;
    float tgt = cz - 0.101f;
    int lo = 0, hi = NN;
    while (lo < hi) { int mid = (lo + hi) >> 1; if (pb[mid].z < tgt) lo = mid + 1; else hi = mid; }
    float zhi = cz + 0.101f;
    int cnt = 0, first = 0x7fffffff;
    for (int j0 = lo; ; j0 += 32) {
        int j = j0 + lane;
        bool inw = false, valid = false; int oi = 0x7fffffff;
        if (j < NN) {
            float4 p = pb[j];
            if (p.z <= zhi) {
                inw = true;
                float dt = (cx*p.x + cy*p.y) + cz*p.z;
                float d2 = cn2 + p.w - 2.f*dt;
                if (d2 < R2) { valid = true; oi = si[j]; }
            }
        }
        if (__ballot_sync(0xffffffffu, inw) == 0u) break;
        unsigned vm = __ballot_sync(0xffffffffu, valid);
        if (vm) {
            int mn = __reduce_min_sync(0xffffffffu, oi);
            first = min(first, mn);
            int pos = cnt + __popc(vm & ((1u << lane) - 1u));
            if (valid && pos < 32) g_bidx[gw*32 + pos] = oi;
            cnt += __popc(vm);
        }
    }
    if (cnt > 32) cnt = 32;
    for (int s = cnt + lane; s < 32; s += 32) g_bidx[gw*32 + s] = first;
    if (lane == 0) g_bcnt[gw] = cnt;
}

// ====== SA conv + max: 8 centers/block, 2-way ILP over samples ======
__global__ void __launch_bounds__(128) k_sa(const float* __restrict__ W,
                                            const float* __restrict__ bias) {
    __shared__ float feat[32][68];
    int t = threadIdx.x;
    float w[67];
#pragma unroll
    for (int j = 0; j < 67; ++j) w[j] = W[j*128 + t];
    float bb = bias[t];
    const float* p4 = (const float*)g_pts4;
#pragma unroll 1
    for (int s = 0; s < 8; ++s) {
        int cid = blockIdx.x*8 + s;
        int b = cid / MM;
        int cnt = g_bcnt[cid];
        float4 cc = g_ctr4[cid];
        __syncthreads();
        for (int i = t; i < cnt*64; i += 128) {
            int k = i >> 6, c = i & 63;
            int idx = g_bidx[cid*32 + k];
            feat[k][3+c] = g_f0[((size_t)b*NN + idx)*64 + c];
        }
        for (int i = t; i < cnt*3; i += 128) {
            int k = i/3, c = i - k*3;
            int idx = g_bidx[cid*32 + k];
            float pv = p4[((size_t)b*NN + idx)*4 + c];
            float cv = (c == 0) ? cc.x : ((c == 1) ? cc.y : cc.z);
            feat[k][c] = (pv - cv) / 0.1f;
        }
        __syncthreads();
        float mx = 0.f;                   // relu >= 0 so max-with-0 exact
        int k = 0;
        for (; k + 2 <= cnt; k += 2) {    // two independent chains (ILP)
            float a0 = bb, a1 = bb;
#pragma unroll
            for (int j = 0; j < 67; ++j) {
                a0 = fmaf(feat[k][j],   w[j], a0);
                a1 = fmaf(feat[k+1][j], w[j], a1);
            }
            mx = fmaxf(mx, fmaxf(a0, a1));
        }
        if (k < cnt) {
            float a0 = bb;
#pragma unroll
            for (int j = 0; j < 67; ++j) a0 = fmaf(feat[k][j], w[j], a0);
            mx = fmaxf(mx, a0);
        }
        g_fsub[(size_t)cid*128 + t] = mx;
    }
}

// ---- insert / score macros ----
#define SC(q) fmaf(px2, (q).x, fmaf(py2, (q).y, fmaf(pz2, (q).z, (q).w)))

#define INS3(s, jj) \
    if ((s) < d2v) { \
        if ((s) < d1) { d2v = d1; i2 = i1; \
            if ((s) < d0) { d1 = d0; i1 = i0; d0 = (s); i0 = (jj); } \
            else          { d1 = (s); i1 = (jj); } } \
        else { d2v = (s); i2 = (jj); } }

#define MAX10 dmax = fmaxf(fmaxf(fmaxf(fmaxf(d[0],d[1]),fmaxf(d[2],d[3])), \
                     fmaxf(fmaxf(d[4],d[5]),fmaxf(d[6],d[7]))),fmaxf(d[8],d[9]));

#define REP10(s, jj) { \
    float _m = dmax; \
    _Pragma("unroll") \
    for (int k = 0; k < 10; ++k) { if (d[k] == _m) { d[k] = (s); id[k] = (jj); } } \
    MAX10 \
}

#define EGRP8(jj, off) { \
    float4 q0 = sj[jj],   q1 = sj[(jj)+1], q2 = sj[(jj)+2], q3 = sj[(jj)+3]; \
    float4 q4 = sj[(jj)+4], q5 = sj[(jj)+5], q6 = sj[(jj)+6], q7 = sj[(jj)+7]; \
    float s0 = SC(q0), s1 = SC(q1), s2 = SC(q2), s3 = SC(q3); \
    float s4 = SC(q4), s5 = SC(q5), s6 = SC(q6), s7 = SC(q7); \
    float m8 = fminf(fminf(fminf(s0,s1), fminf(s2,s3)), \
                     fminf(fminf(s4,s5), fminf(s6,s7))); \
    if (m8 < dmax) { \
        if (s0 < dmax) REP10(s0, (off)+(jj)) \
        if (s1 < dmax) REP10(s1, (off)+(jj)+1) \
        if (s2 < dmax) REP10(s2, (off)+(jj)+2) \
        if (s3 < dmax) REP10(s3, (off)+(jj)+3) \
        if (s4 < dmax) REP10(s4, (off)+(jj)+4) \
        if (s5 < dmax) REP10(s5, (off)+(jj)+5) \
        if (s6 < dmax) REP10(s6, (off)+(jj)+6) \
        if (s7 < dmax) REP10(s7, (off)+(jj)+7) \
    } \
}

#define KSCAN128(base) { \
    for (int j = 0; j < 128; j += 8) { \
        float4 q0 = sbuf[j],   q1 = sbuf[j+1], q2 = sbuf[j+2], q3 = sbuf[j+3]; \
        float4 q4 = sbuf[j+4], q5 = sbuf[j+5], q6 = sbuf[j+6], q7 = sbuf[j+7]; \
        float s0 = SC(q0), s1 = SC(q1), s2 = SC(q2), s3 = SC(q3); \
        float s4 = SC(q4), s5 = SC(q5), s6 = SC(q6), s7 = SC(q7); \
        float m8 = fminf(fminf(fminf(s0,s1), fminf(s2,s3)), \
                         fminf(fminf(s4,s5), fminf(s6,s7))); \
        if (m8 < d2v) { \
            INS3(s0, (base)+j)   INS3(s1, (base)+j+1) INS3(s2, (base)+j+2) INS3(s3, (base)+j+3) \
            INS3(s4, (base)+j+4) INS3(s5, (base)+j+5) INS3(s6, (base)+j+6) INS3(s7, (base)+j+7) \
        } \
    } }

// ===== fused scans: blocks [0,128) = 10-NN+eig, [128,256) = 3-NN =====
__global__ void __launch_bounds__(256) k_scan(
        const float* __restrict__ We1, const float* __restrict__ be1,
        const float* __restrict__ We2, const float* __restrict__ be2) {
    __shared__ float4 sbuf[256];          // 4KB, shared by both branches
    int blk = blockIdx.x;
    int t = threadIdx.x;

    if (blk < 128) {
        // ---- 10-NN: 256-point chunks, ring order + cov/eigvalsh/MLP ----
        float4* sj = sbuf;
        int b = blk >> 4, l = blk & 15;
        int q = (l << 8) + t;
        const float4* pb = g_spts + (size_t)b*NN;
        float4 pp = pb[q];
        int pid = (b << 12) + g_sidx[(size_t)b*NN + q];
        float zi = pp.z, pn2 = pp.w;
        float px2 = -2.f*pp.x, py2 = -2.f*pp.y, pz2 = -2.f*pp.z;
        float d[10]; int id[10];
#pragma unroll
        for (int k = 0; k < 10; ++k) { d[k] = 1e37f + (float)k*1e33f; id[k] = q; }
        float dmax = d[9];
        int c0 = l;                       // own 256-chunk (16 chunks total)
        {
            int base = c0 << 8;
            sj[t] = pb[base + t];
            __syncthreads();
            for (int j = 0; j < 256; j += 8) { EGRP8(j, base) }
        }
        bool needL = true, needR = true;
#pragma unroll 1
        for (int step = 1; step <= 15; ++step) {
            int cl = c0 - step, cr = c0 + step;
            {   // left
                bool far = true;
                if (needL && cl >= 0) {
                    float ze = pb[(cl << 8) + 255].z;
                    float dz = zi - ze;
                    far = (dz > 0.f) && (dz*dz > fmaf(dmax + pn2, 1.0001f, 1e-9f));
                }
                if (__syncthreads_and(far)) needL = false;
                if (needL && cl >= 0) {
                    int base = cl << 8;
                    __syncthreads();
                    sj[t] = pb[base + t];
                    __syncthreads();
                    for (int j = 0; j < 256; j += 8) { EGRP8(j, base) }
                }
            }
            {   // right
                bool far = true;
                if (needR && cr < 16) {
                    float ze = pb[cr << 8].z;
                    float dz = ze - zi;
                    far = (dz > 0.f) && (dz*dz > fmaf(dmax + pn2, 1.0001f, 1e-9f));
                }
                if (__syncthreads_and(far)) needR = false;
                if (needR && cr < 16) {
                    int base = cr << 8;
                    __syncthreads();
                    sj[t] = pb[base + t];
                    __syncthreads();
                    for (int j = 0; j < 256; j += 8) { EGRP8(j, base) }
                }
            }
            if (!(needL | needR)) break;
        }
        // gather + mean + covariance (order-invariant)
        float nx[10], ny[10], nz[10];
        float mx = 0.f, my = 0.f, mz = 0.f;
#pragma unroll
        for (int k = 0; k < 10; ++k) {
            float4 qq = pb[id[k]];
            nx[k] = qq.x; ny[k] = qq.y; nz[k] = qq.z;
            mx += qq.x; my += qq.y; mz += qq.z;
        }
        mx /= 10.f; my /= 10.f; mz /= 10.f;
        float cxx=0,cxy=0,cxz=0,cyy=0,cyz=0,czz=0;
#pragma unroll
        for (int k = 0; k < 10; ++k) {
            float dx = nx[k]-mx, dy = ny[k]-my, dz = nz[k]-mz;
            cxx += dx*dx; cxy += dx*dy; cxz += dx*dz;
            cyy += dy*dy; cyz += dy*dz; czz += dz*dz;
        }
        cxx /= 10.f; cxy /= 10.f; cxz /= 10.f; cyy /= 10.f; cyz /= 10.f; czz /= 10.f;
        double a00=cxx, a01=cxy, a02=cxz, a11=cyy, a12=cyz, a22=czz;
        double qd  = (a00 + a11 + a22) / 3.0;
        double p1 = a01*a01 + a02*a02 + a12*a12;
        double b00 = a00 - qd, b11 = a11 - qd, b22 = a22 - qd;
        double p2 = b00*b00 + b11*b11 + b22*b22 + 2.0*p1;
        double e0, e1, e2;
        if (p2 < 1e-60) { e0 = e1 = e2 = qd; }
        else {
            double p  = sqrt(p2 / 6.0);
            double ip = 1.0 / p;
            double c00=b00*ip, c11=b11*ip, c22=b22*ip, c01=a01*ip, c02=a02*ip, c12=a12*ip;
            double detB = c00*(c11*c22 - c12*c12) - c01*(c01*c22 - c12*c02)
                        + c02*(c01*c12 - c11*c02);
            double r = 0.5 * detB;
            r = fmin(1.0, fmax(-1.0, r));
            double phi = acos(r) / 3.0;
            double l1 = qd + 2.0*p*cos(phi);
            double l3 = qd + 2.0*p*cos(phi + 2.0943951023931953);
            double l2 = 3.0*qd - l1 - l3;
            e0 = l3; e1 = l2; e2 = l1;    // ascending
        }
        float ev0 = (float)e0, ev1 = (float)e1, ev2 = (float)e2;
        float hh[4];
#pragma unroll
        for (int i = 0; i < 4; ++i) {
            float v = fmaf(ev0, We1[i], fmaf(ev1, We1[4+i], fmaf(ev2, We1[8+i], be1[i])));
            hh[i] = fmaxf(v, 0.f);
        }
#pragma unroll
        for (int i = 0; i < 4; ++i) {
            float v = be2[i];
#pragma unroll
            for (int j = 0; j < 4; ++j) v = fmaf(hh[j], We2[j*4+i], v);
            g_ef[(size_t)pid*4 + i] = v;
        }

    } else {
        // ---- 3-NN: 128-center chunks over sorted centers, ring order ----
        int idx = blk - 128;
        int b = idx >> 4, l = idx & 15;
        int q = (l << 8) + t;
        const float4* pb = g_spts + (size_t)b*NN;
        const float4* cb = g_sctr + b*CPAD;
        float4 pp = pb[q];
        int pid = (b << 12) + g_sidx[(size_t)b*NN + q];
        float zi = pp.z, pn2 = pp.w;
        float px2 = -2.f*pp.x, py2 = -2.f*pp.y, pz2 = -2.f*pp.z;
        float d0 = 1e37f, d1 = 1e37f, d2v = 1e37f;
        int i0 = 0, i1 = 0, i2 = 0;
        int qm = (l << 8) + 128;
        int c0 = (qm * MM / NN) >> 7; if (c0 > 10) c0 = 10;   // block-uniform
        {
            int base = c0 << 7;
            if (t < 128) sbuf[t] = cb[base + t];
            __syncthreads();
            KSCAN128(base)
        }
        bool needL = true, needR = true;
#pragma unroll 1
        for (int step = 1; step <= 15; ++step) {
            int cl = c0 - step, cr = c0 + step;
            {   // left
                bool far = true;
                if (needL && cl >= 0) {
                    float ze = cb[(cl << 7) + 127].z;
                    float dz = zi - ze;
                    far = (dz > 0.f) && (dz*dz > fmaf(d2v + pn2, 1.0001f, 1e-9f));
                }
                if (__syncthreads_and(far)) needL = false;
                if (needL && cl >= 0) {
                    int base = cl << 7;
                    __syncthreads();
                    if (t < 128) sbuf[t] = cb[base + t];
                    __syncthreads();
                    KSCAN128(base)
                }
            }
            {   // right
                bool far = true;
                if (needR && cr < 16) {
                    float ze = cb[cr << 7].z;
                    float dz = ze - zi;
                    far = (dz > 0.f) && (dz*dz > fmaf(d2v + pn2, 1.0001f, 1e-9f));
                }
                if (__syncthreads_and(far)) needR = false;
                if (needR && cr < 16) {
                    int base = cr << 7;
                    __syncthreads();
                    if (t < 128) sbuf[t] = cb[base + t];
                    __syncthreads();
                    KSCAN128(base)
                }
            }
            if (!needL && !needR) break;
        }
        i0 = g_scidx[b*CPAD + i0];
        i1 = g_scidx[b*CPAD + i1];
        i2 = g_scidx[b*CPAD + i2];
        float D0 = d0 + pn2, D1 = d1 + pn2, D2 = d2v + pn2;
        float w0 = 1.f/(D0 + 1e-8f), w1 = 1.f/(D1 + 1e-8f), w2 = 1.f/(D2 + 1e-8f);
        float ws = (w0 + w1) + w2;
        w0 /= ws; w1 /= ws; w2 /= ws;
        g_nn[pid*3+0] = i0; g_nn[pid*3+1] = i1; g_nn[pid*3+2] = i2;
        g_wts[pid*3+0] = w0; g_wts[pid*3+1] = w1; g_wts[pid*3+2] = w2;
    }
}

// ==== fused interp+FP+final-linear: 64 pts/block, 4x4 blocking, LDS.128 ====
__global__ void __launch_bounds__(256) k_fpzc(
        const float* __restrict__ W,  const float* __restrict__ bias,
        const float* __restrict__ W2, const float* __restrict__ bias2) {
    __shared__ float fs[64][196];         // 50176 B (784B rows: 16B-aligned)
    __shared__ float ssum[64], ssq[64];
    int t = threadIdx.x;
    int g = t >> 4, q = t & 15;
    size_t base = (size_t)blockIdx.x * 64;
#pragma unroll
    for (int i = 0; i < 4; ++i) {
        int p = g*4 + i;
        size_t pid = base + p;
        int b = (int)(pid >> 12);
        int n0 = g_nn[pid*3+0], n1 = g_nn[pid*3+1], n2 = g_nn[pid*3+2];
        float w0 = g_wts[pid*3+0], w1 = g_wts[pid*3+1], w2 = g_wts[pid*3+2];
        size_t a0 = ((size_t)b*MM + n0)*128;
        size_t a1 = ((size_t)b*MM + n1)*128;
        size_t a2 = ((size_t)b*MM + n2)*128;
#pragma unroll
        for (int k = 0; k < 8; ++k) {
            int j = k*16 + q;
            fs[p][j] = (w0*g_fsub[a0+j] + w1*g_fsub[a1+j]) + w2*g_fsub[a2+j];
        }
#pragma unroll
        for (int k = 0; k < 4; ++k) {
            int j = k*16 + q;
            fs[p][128+j] = g_f0[pid*64 + j];
        }
    }
    if (t < 64) { ssum[t] = 0.f; ssq[t] = 0.f; }
    __syncthreads();
    int c4 = q*4;
    int p0 = g*4;
    float4 bi = *(const float4*)&bias[c4];
    float4 a0 = bi, a1 = bi, a2 = bi, a3 = bi;
#pragma unroll 2
    for (int j = 0; j < 192; j += 4) {
        float4 f0 = *(const float4*)&fs[p0+0][j];
        float4 f1 = *(const float4*)&fs[p0+1][j];
        float4 f2 = *(const float4*)&fs[p0+2][j];
        float4 f3 = *(const float4*)&fs[p0+3][j];
#pragma unroll
        for (int u = 0; u < 4; ++u) {
            float4 w4 = *(const float4*)&W[(j+u)*64 + c4];
            float v0 = (u==0)?f0.x:((u==1)?f0.y:((u==2)?f0.z:f0.w));
            float v1 = (u==0)?f1.x:((u==1)?f1.y:((u==2)?f1.z:f1.w));
            float v2 = (u==0)?f2.x:((u==1)?f2.y:((u==2)?f2.z:f2.w));
            float v3 = (u==0)?f3.x:((u==1)?f3.y:((u==2)?f3.z:f3.w));
            a0.x = fmaf(v0, w4.x, a0.x); a0.y = fmaf(v0, w4.y, a0.y);
            a0.z = fmaf(v0, w4.z, a0.z); a0.w = fmaf(v0, w4.w, a0.w);
            a1.x = fmaf(v1, w4.x, a1.x); a1.y = fmaf(v1, w4.y, a1.y);
            a1.z = fmaf(v1, w4.z, a1.z); a1.w = fmaf(v1, w4.w, a1.w);
            a2.x = fmaf(v2, w4.x, a2.x); a2.y = fmaf(v2, w4.y, a2.y);
            a2.z = fmaf(v2, w4.z, a2.z); a2.w = fmaf(v2, w4.w, a2.w);
            a3.x = fmaf(v3, w4.x, a3.x); a3.y = fmaf(v3, w4.y, a3.y);
            a3.z = fmaf(v3, w4.z, a3.z); a3.w = fmaf(v3, w4.w, a3.w);
        }
    }
    __syncthreads();                      // all reads of fs done
    *(float4*)&fs[p0+0][c4] = make_float4(fmaxf(a0.x,0.f), fmaxf(a0.y,0.f), fmaxf(a0.z,0.f), fmaxf(a0.w,0.f));
    *(float4*)&fs[p0+1][c4] = make_float4(fmaxf(a1.x,0.f), fmaxf(a1.y,0.f), fmaxf(a1.z,0.f), fmaxf(a1.w,0.f));
    *(float4*)&fs[p0+2][c4] = make_float4(fmaxf(a2.x,0.f), fmaxf(a2.y,0.f), fmaxf(a2.z,0.f), fmaxf(a2.w,0.f));
    *(float4*)&fs[p0+3][c4] = make_float4(fmaxf(a3.x,0.f), fmaxf(a3.y,0.f), fmaxf(a3.z,0.f), fmaxf(a3.w,0.f));
    if (q < 4) {
#pragma unroll
        for (int i = 0; i < 4; ++i)
            fs[p0+i][64+q] = g_ef[(base+p0+i)*4 + q];
    }
    __syncthreads();
    float4 bi2 = *(const float4*)&bias2[c4];
    a0 = bi2; a1 = bi2; a2 = bi2; a3 = bi2;
#pragma unroll
    for (int j = 0; j < 68; j += 4) {
        float4 f0 = *(const float4*)&fs[p0+0][j];
        float4 f1 = *(const float4*)&fs[p0+1][j];
        float4 f2 = *(const float4*)&fs[p0+2][j];
        float4 f3 = *(const float4*)&fs[p0+3][j];
#pragma unroll
        for (int u = 0; u < 4; ++u) {
            float4 w4 = *(const float4*)&W2[(j+u)*64 + c4];
            float v0 = (u==0)?f0.x:((u==1)?f0.y:((u==2)?f0.z:f0.w));
            float v1 = (u==0)?f1.x:((u==1)?f1.y:((u==2)?f1.z:f1.w));
            float v2 = (u==0)?f2.x:((u==1)?f2.y:((u==2)?f2.z:f2.w));
            float v3 = (u==0)?f3.x:((u==1)?f3.y:((u==2)?f3.z:f3.w));
            a0.x = fmaf(v0, w4.x, a0.x); a0.y = fmaf(v0, w4.y, a0.y);
            a0.z = fmaf(v0, w4.z, a0.z); a0.w = fmaf(v0, w4.w, a0.w);
            a1.x = fmaf(v1, w4.x, a1.x); a1.y = fmaf(v1, w4.y, a1.y);
            a1.z = fmaf(v1, w4.z, a1.z); a1.w = fmaf(v1, w4.w, a1.w);
            a2.x = fmaf(v2, w4.x, a2.x); a2.y = fmaf(v2, w4.y, a2.y);
            a2.z = fmaf(v2, w4.z, a2.z); a2.w = fmaf(v2, w4.w, a2.w);
            a3.x = fmaf(v3, w4.x, a3.x); a3.y = fmaf(v3, w4.y, a3.y);
            a3.z = fmaf(v3, w4.z, a3.z); a3.w = fmaf(v3, w4.w, a3.w);
        }
    }
    *(float4*)&g_zc[(base+p0+0)*64 + c4] = a0;
    *(float4*)&g_zc[(base+p0+1)*64 + c4] = a1;
    *(float4*)&g_zc[(base+p0+2)*64 + c4] = a2;
    *(float4*)&g_zc[(base+p0+3)*64 + c4] = a3;
    float sx = ((a0.x + a1.x) + (a2.x + a3.x));
    float sy = ((a0.y + a1.y) + (a2.y + a3.y));
    float sz = ((a0.z + a1.z) + (a2.z + a3.z));
    float sw = ((a0.w + a1.w) + (a2.w + a3.w));
    float qx = ((a0.x*a0.x + a1.x*a1.x) + (a2.x*a2.x + a3.x*a3.x));
    float qy = ((a0.y*a0.y + a1.y*a1.y) + (a2.y*a2.y + a3.y*a3.y));
    float qz = ((a0.z*a0.z + a1.z*a1.z) + (a2.z*a2.z + a3.z*a3.z));
    float qw = ((a0.w*a0.w + a1.w*a1.w) + (a2.w*a2.w + a3.w*a3.w));
    atomicAdd(&ssum[c4+0], sx); atomicAdd(&ssum[c4+1], sy);
    atomicAdd(&ssum[c4+2], sz); atomicAdd(&ssum[c4+3], sw);
    atomicAdd(&ssq[c4+0], qx);  atomicAdd(&ssq[c4+1], qy);
    atomicAdd(&ssq[c4+2], qz);  atomicAdd(&ssq[c4+3], qw);
    __syncthreads();
    if (t < 64) {
        atomicAdd(&g_sum[t], (double)ssum[t]);
        atomicAdd(&g_sq[t],  (double)ssq[t]);
    }
}

__global__ void k_stats() {
    int c = threadIdx.x;
    if (c < 64) {
        double mu  = g_sum[c] / (double)NPTS;
        double var = g_sq[c] / (double)NPTS - mu*mu;
        g_mu[c]  = (float)mu;
        g_inv[c] = rsqrtf((float)var + 1e-5f);
    }
}

// ======= normalize + relu + transpose via smem tiles =======
__global__ void k_norm(const float* __restrict__ gamma, const float* __restrict__ beta,
                       float* __restrict__ outz) {
    __shared__ float tile[32][33];
    int b   = blockIdx.x >> 8;            // 256 blocks per batch
    int rem = blockIdx.x & 255;
    int ct  = rem >> 7;                   // 2 channel tiles
    int nt  = rem & 127;                  // 128 point tiles
    int tx = threadIdx.x, ty = threadIdx.y;
    int c = ct*32 + tx;
    float mu = g_mu[c], inv = g_inv[c], ga = gamma[c], be = beta[c];
#pragma unroll
    for (int i = 0; i < 4; ++i) {
        int n = nt*32 + ty + i*8;
        float v = g_zc[(((size_t)(b<<12) + n) << 6) + c];
        v = (v - mu) * inv * ga + be;
        tile[ty + i*8][tx] = fmaxf(v, 0.f);
    }
    __syncthreads();
#pragma unroll
    for (int i = 0; i < 4; ++i) {
        int cc = ct*32 + ty + i*8;
        int n  = nt*32 + tx;
        outz[(((size_t)b*64 + cc) << 12) + n] = tile[tx][ty + i*8];
    }
}

// ================= launch =================
extern "C" void kernel_launch(void* const* d_in, const int* in_sizes, int n_in,
                              void* d_out, int out_size) {
    const float* data = (const float*)d_in[0];
    int o = 1;
    if (n_in >= 16 && in_sizes[1] == 1) o = 2;   // skip scalar 'numpoints'
    const float* W_stem = (const float*)d_in[o+0];
    const float* b_stem = (const float*)d_in[o+1];
    const float* W_sa   = (const float*)d_in[o+2];
    const float* b_sa   = (const float*)d_in[o+3];
    const float* W_fp   = (const float*)d_in[o+4];
    const float* b_fp   = (const float*)d_in[o+5];
    const float* W_e1   = (const float*)d_in[o+6];
    const float* b_e1   = (const float*)d_in[o+7];
    const float* W_e2   = (const float*)d_in[o+8];
    const float* b_e2   = (const float*)d_in[o+9];
    const float* W_fin  = (const float*)d_in[o+10];
    const float* b_fin  = (const float*)d_in[o+11];
    const float* gamma  = (const float*)d_in[o+12];
    const float* beta   = (const float*)d_in[o+13];
    float* out = (float*)d_out;
    size_t zoff = ((size_t)out_size == (size_t)BB*64*NN) ? 0 : (size_t)NPTS*3;

    k_stem<<<NPTS/4, 256>>>(data, W_stem, b_stem, zoff ? out : (float*)0);
    k_sort<<<2*BB, 1024>>>();
    k_ball<<<BB*86, 512>>>();
    k_sa<<<NCTR/8, 128>>>(W_sa, b_sa);
    k_scan<<<256, 256>>>(W_e1, b_e1, W_e2, b_e2);
    k_fpzc<<<NPTS/64, 256>>>(W_fp, b_fp, W_fin, b_fin);
    k_stats<<<1, 64>>>();
    dim3 nb(32, 8);
    k_norm<<<BB*256, nb>>>(gamma, beta, out + zoff);
}